// round 5
// baseline (speedup 1.0000x reference)
#include <cuda_runtime.h>

// DWTExtractor: 2-level Haar DWT + bilinear 2x upsample of level-2 details.
// Input:  (32, 1, 1024, 1024) fp32 -> Output: (32, 6, 512, 512) fp32
//          [cH1, cV1, cD1, up(cH2), up(cV2), up(cD2)]
//
// Block = one 64x64 output tile, all 6 channels, one batch image.
//  Part 1: central 32x32 level-2 cells as 256 pairs x2 iters. Each thread:
//          8 LDG.128 (4x8 input patch), level-2 -> smem, level-1 2x4 block
//          -> 6 x STG.128 streaming.
//  Part 2: 132-cell halo ring, level-2 -> smem only (clamped == jax renorm).
//  Part 3: separable half-pixel bilinear (0.75/0.25), 8 outputs/thread,
//          vector LDS (16B-aligned rows, stride 36), float4 streaming stores.

#define TS    64
#define H2_T  34
#define H2_S  36   // row stride (floats): 144B rows -> 16B-aligned

__device__ __forceinline__ void cell_compute(
    const float* __restrict__ inb, int r, int c,
    float& l2h, float& l2v, float& l2d,
    float2& hT, float2& vT, float2& dT,
    float2& hB, float2& vB, float2& dB)
{
    const float4 v0 = *((const float4*)(inb + (size_t)(4 * r    ) * 1024) + c);
    const float4 v1 = *((const float4*)(inb + (size_t)(4 * r + 1) * 1024) + c);
    const float4 v2 = *((const float4*)(inb + (size_t)(4 * r + 2) * 1024) + c);
    const float4 v3 = *((const float4*)(inb + (size_t)(4 * r + 3) * 1024) + c);

    const float s0l = v0.x + v0.y, d0l = v0.x - v0.y;
    const float s0r = v0.z + v0.w, d0r = v0.z - v0.w;
    const float s1l = v1.x + v1.y, d1l = v1.x - v1.y;
    const float s1r = v1.z + v1.w, d1r = v1.z - v1.w;
    const float s2l = v2.x + v2.y, d2l = v2.x - v2.y;
    const float s2r = v2.z + v2.w, d2r = v2.z - v2.w;
    const float s3l = v3.x + v3.y, d3l = v3.x - v3.y;
    const float s3r = v3.z + v3.w, d3r = v3.z - v3.w;

    const float a00 = s0l + s1l, a01 = s0r + s1r;
    const float a10 = s2l + s3l, a11 = s2r + s3r;
    l2h = (a00 - a01 + a10 - a11) * 0.25f;
    l2v = (a00 + a01 - a10 - a11) * 0.25f;
    l2d = (a00 - a01 - a10 + a11) * 0.25f;

    hT = make_float2((d0l + d1l) * 0.5f, (d0r + d1r) * 0.5f);
    vT = make_float2((s0l - s1l) * 0.5f, (s0r - s1r) * 0.5f);
    dT = make_float2((d0l - d1l) * 0.5f, (d0r - d1r) * 0.5f);
    hB = make_float2((d2l + d3l) * 0.5f, (d2r + d3r) * 0.5f);
    vB = make_float2((s2l - s3l) * 0.5f, (s2r - s3r) * 0.5f);
    dB = make_float2((d2l - d3l) * 0.5f, (d2r - d3r) * 0.5f);
}

__global__ __launch_bounds__(256, 7)
void dwt_fused_kernel(const float* __restrict__ in, float* __restrict__ out)
{
    __shared__ __align__(16) float sH[H2_T * H2_S];
    __shared__ __align__(16) float sV[H2_T * H2_S];
    __shared__ __align__(16) float sD[H2_T * H2_S];

    const int b   = blockIdx.z;
    const int oy0 = blockIdx.y * TS;
    const int ox0 = blockIdx.x * TS;
    const int tid = threadIdx.x;

    const float* __restrict__ inb  = in  + (size_t)b * 1024 * 1024;
    float* __restrict__       outb = out + (size_t)b * 6 * 512 * 512;

    const int r0g = oy0 >> 1;   // level-2 tile origin on the 256-grid
    const int c0g = ox0 >> 1;

    // ---- Part 1: central 32x32 level-2 cells, processed as pairs ----
    #pragma unroll 1
    for (int i = tid; i < 512; i += 256) {
        const int pr = i >> 4;        // 0..31
        const int pc = i & 15;        // 0..15
        const int lr = pr + 1;        // smem row (1..32)
        const int lc = 2 * pc + 1;    // smem col of left cell (1,3,..,31)
        const int rr = r0g + pr;      // 256-grid row (in range, no clamp)
        const int cc = c0g + 2 * pc;  // 256-grid col of left cell

        float l2hA, l2vA, l2dA, l2hB, l2vB, l2dB;
        float2 hTa, vTa, dTa, hBa, vBa, dBa;
        float2 hTb, vTb, dTb, hBb, vBb, dBb;
        cell_compute(inb, rr, cc,     l2hA, l2vA, l2dA, hTa, vTa, dTa, hBa, vBa, dBa);
        cell_compute(inb, rr, cc + 1, l2hB, l2vB, l2dB, hTb, vTb, dTb, hBb, vBb, dBb);

        sH[lr * H2_S + lc] = l2hA;  sH[lr * H2_S + lc + 1] = l2hB;
        sV[lr * H2_S + lc] = l2vA;  sV[lr * H2_S + lc + 1] = l2vB;
        sD[lr * H2_S + lc] = l2dA;  sD[lr * H2_S + lc + 1] = l2dB;

        // level-1 2x4 block: rows 2rr,2rr+1; cols 2cc..2cc+3 (float4-aligned)
        const size_t oT = ((size_t)(2 * rr) * 512 + 2 * cc) >> 2;  // float4 idx
        const size_t oB = oT + 128;                                // next row
        float4* o4 = (float4*)outb;
        __stcs(o4 + 0 * 65536 + oT, make_float4(hTa.x, hTa.y, hTb.x, hTb.y));
        __stcs(o4 + 0 * 65536 + oB, make_float4(hBa.x, hBa.y, hBb.x, hBb.y));
        __stcs(o4 + 1 * 65536 + oT, make_float4(vTa.x, vTa.y, vTb.x, vTb.y));
        __stcs(o4 + 1 * 65536 + oB, make_float4(vBa.x, vBa.y, vBb.x, vBb.y));
        __stcs(o4 + 2 * 65536 + oT, make_float4(dTa.x, dTa.y, dTb.x, dTb.y));
        __stcs(o4 + 2 * 65536 + oB, make_float4(dBa.x, dBa.y, dBb.x, dBb.y));
    }

    // ---- Part 2: halo ring (132 cells), level-2 smem only, clamped ----
    if (tid < 132) {
        int lr, lc;
        if (tid < 34)       { lr = 0;         lc = tid;        }
        else if (tid < 68)  { lr = 33;        lc = tid - 34;   }
        else if (tid < 100) { lr = tid - 67;  lc = 0;          }
        else                { lr = tid - 99;  lc = 33;         }
        const int r = min(max(r0g - 1 + lr, 0), 255);
        const int c = min(max(c0g - 1 + lc, 0), 255);

        float l2h, l2v, l2d;
        float2 t0, t1, t2, t3, t4, t5;
        cell_compute(inb, r, c, l2h, l2v, l2d, t0, t1, t2, t3, t4, t5);
        sH[lr * H2_S + lc] = l2h;
        sV[lr * H2_S + lc] = l2v;
        sD[lr * H2_S + lc] = l2d;
    }

    __syncthreads();

    // ---- Part 3: bilinear 2x upsample, 8 horizontal outputs/thread ----
    // out[2k] = 0.25*v[k-1]+0.75*v[k],  out[2k+1] = 0.75*v[k]+0.25*v[k+1]
    #pragma unroll 1
    for (int i = tid; i < 512; i += 256) {
        const int y  = i >> 3;         // 0..63
        const int xo = i & 7;          // col group: x = 8*xo .. 8*xo+7
        const int ky = (y >> 1) + 1;
        const int ry0 = (y & 1) ? ky     : ky - 1;
        const int ry1 = (y & 1) ? ky + 1 : ky;
        const float wy0 = (y & 1) ? 0.75f : 0.25f;
        const float wy1 = 1.0f - wy0;

        const int cb = 4 * xo;                // local cols cb..cb+5 used
        const int A0 = ry0 * H2_S + cb;       // 16B-aligned
        const int A1 = ry1 * H2_S + cb;

        const size_t o4 = ((size_t)(oy0 + y) * 512 + ox0 + 8 * xo) >> 2;
        float4* op = (float4*)outb;

        #pragma unroll
        for (int ch = 0; ch < 3; ch++) {
            const float* s = (ch == 0) ? sH : (ch == 1) ? sV : sD;
            const float4 a4 = *(const float4*)(s + A0);
            const float2 a2 = *(const float2*)(s + A0 + 4);
            const float4 b4 = *(const float4*)(s + A1);
            const float2 b2 = *(const float2*)(s + A1 + 4);
            const float m0 = wy0 * a4.x + wy1 * b4.x;
            const float m1 = wy0 * a4.y + wy1 * b4.y;
            const float m2 = wy0 * a4.z + wy1 * b4.z;
            const float m3 = wy0 * a4.w + wy1 * b4.w;
            const float m4 = wy0 * a2.x + wy1 * b2.x;
            const float m5 = wy0 * a2.y + wy1 * b2.y;

            const float4 r0 = make_float4(0.25f * m0 + 0.75f * m1,
                                          0.75f * m1 + 0.25f * m2,
                                          0.25f * m1 + 0.75f * m2,
                                          0.75f * m2 + 0.25f * m3);
            const float4 r1 = make_float4(0.25f * m2 + 0.75f * m3,
                                          0.75f * m3 + 0.25f * m4,
                                          0.25f * m3 + 0.75f * m4,
                                          0.75f * m4 + 0.25f * m5);
            __stcs(op + (size_t)(3 + ch) * 65536 + o4,     r0);
            __stcs(op + (size_t)(3 + ch) * 65536 + o4 + 1, r1);
        }
    }
}

extern "C" void kernel_launch(void* const* d_in, const int* in_sizes, int n_in,
                              void* d_out, int out_size)
{
    const float* x = (const float*)d_in[0];
    float* out = (float*)d_out;
    dim3 grid(512 / TS, 512 / TS, 32);   // (8, 8, 32) = 2048 blocks
    dwt_fused_kernel<<<grid, 256>>>(x, out);
}

// round 7
// speedup vs baseline: 1.1552x; 1.1552x over previous
#include <cuda_runtime.h>

// DWTExtractor: 2-level Haar DWT + bilinear 2x upsample of level-2 details.
// Input:  (32, 1, 1024, 1024) fp32 -> Output: (32, 6, 512, 512) fp32
//          [cH1, cV1, cD1, up(cH2), up(cV2), up(cD2)]
//
// Block = one 64x64 output tile, all 6 channels, one batch image. 7 CTAs/SM
// -> 1036 concurrent blocks, 2048 total = ~2.0 clean waves.
//  Part 1: central 32x32 level-2 cells, 1 cell/thread, 4 iterations.
//          Lanes map to consecutive float4 columns (fully coalesced LDG.128).
//          Each cell: 4x4 input patch -> level-2 coeffs to smem + 2x2 level-1
//          detail block to gmem (float2 streaming stores, coalesced).
//  Part 2: 132-cell halo ring, level-2 smem only (clamped == jax resize
//          weight renormalization at edges).
//  Part 3: separable half-pixel bilinear (0.75/0.25), 8 outputs/thread,
//          vector LDS (rows 16B-aligned, stride 36), float4 streaming stores.

#define TS    64
#define H2_T  34
#define H2_S  36   // smem row stride (floats): 144B -> 16B-aligned rows

__device__ __forceinline__ void cell_compute(
    const float* __restrict__ inb, int r, int c,
    float& l2h, float& l2v, float& l2d,
    float2& hT, float2& vT, float2& dT,
    float2& hB, float2& vB, float2& dB)
{
    const float4 v0 = *((const float4*)(inb + (size_t)(4 * r    ) * 1024) + c);
    const float4 v1 = *((const float4*)(inb + (size_t)(4 * r + 1) * 1024) + c);
    const float4 v2 = *((const float4*)(inb + (size_t)(4 * r + 2) * 1024) + c);
    const float4 v3 = *((const float4*)(inb + (size_t)(4 * r + 3) * 1024) + c);

    const float s0l = v0.x + v0.y, d0l = v0.x - v0.y;
    const float s0r = v0.z + v0.w, d0r = v0.z - v0.w;
    const float s1l = v1.x + v1.y, d1l = v1.x - v1.y;
    const float s1r = v1.z + v1.w, d1r = v1.z - v1.w;
    const float s2l = v2.x + v2.y, d2l = v2.x - v2.y;
    const float s2r = v2.z + v2.w, d2r = v2.z - v2.w;
    const float s3l = v3.x + v3.y, d3l = v3.x - v3.y;
    const float s3r = v3.z + v3.w, d3r = v3.z - v3.w;

    const float a00 = s0l + s1l, a01 = s0r + s1r;
    const float a10 = s2l + s3l, a11 = s2r + s3r;
    l2h = (a00 - a01 + a10 - a11) * 0.25f;   // 0.5 haar * 0.5 folded cA1
    l2v = (a00 + a01 - a10 - a11) * 0.25f;
    l2d = (a00 - a01 - a10 + a11) * 0.25f;

    hT = make_float2((d0l + d1l) * 0.5f, (d0r + d1r) * 0.5f);
    vT = make_float2((s0l - s1l) * 0.5f, (s0r - s1r) * 0.5f);
    dT = make_float2((d0l - d1l) * 0.5f, (d0r - d1r) * 0.5f);
    hB = make_float2((d2l + d3l) * 0.5f, (d2r + d3r) * 0.5f);
    vB = make_float2((s2l - s3l) * 0.5f, (s2r - s3r) * 0.5f);
    dB = make_float2((d2l - d3l) * 0.5f, (d2r - d3r) * 0.5f);
}

__global__ __launch_bounds__(256, 7)
void dwt_fused_kernel(const float* __restrict__ in, float* __restrict__ out)
{
    __shared__ __align__(16) float sH[H2_T * H2_S];
    __shared__ __align__(16) float sV[H2_T * H2_S];
    __shared__ __align__(16) float sD[H2_T * H2_S];

    const int b   = blockIdx.z;
    const int oy0 = blockIdx.y * TS;
    const int ox0 = blockIdx.x * TS;
    const int tid = threadIdx.x;

    const float* __restrict__ inb  = in  + (size_t)b * 1024 * 1024;
    float* __restrict__       outb = out + (size_t)b * 6 * 512 * 512;

    const int r0g = oy0 >> 1;   // level-2 tile origin on the 256-grid
    const int c0g = ox0 >> 1;

    // ---- Part 1: central 32x32 level-2 cells (no clamps, shift indexing) ----
    #pragma unroll 1
    for (int it = 0; it < 4; it++) {
        const int idx = it * 256 + tid;
        const int col = idx & 31;          // lane -> column: coalesced loads
        const int row = idx >> 5;          // 0..31
        const int rr = r0g + row;
        const int cc = c0g + col;

        float l2h, l2v, l2d;
        float2 hT, vT, dT, hB, vB, dB;
        cell_compute(inb, rr, cc, l2h, l2v, l2d, hT, vT, dT, hB, vB, dB);

        sH[(row + 1) * H2_S + col + 1] = l2h;
        sV[(row + 1) * H2_S + col + 1] = l2v;
        sD[(row + 1) * H2_S + col + 1] = l2d;

        // level-1 2x2 block: rows 2rr,2rr+1; cols 2cc,2cc+1 (float2 stores)
        const size_t oT = ((size_t)(2 * rr) * 512 + 2 * cc) >> 1;  // float2 idx
        const size_t oB = oT + 256;
        float2* o2 = (float2*)outb;
        __stcs(o2 + 0 * 131072 + oT, hT);
        __stcs(o2 + 0 * 131072 + oB, hB);
        __stcs(o2 + 1 * 131072 + oT, vT);
        __stcs(o2 + 1 * 131072 + oB, vB);
        __stcs(o2 + 2 * 131072 + oT, dT);
        __stcs(o2 + 2 * 131072 + oB, dB);
    }

    // ---- Part 2: halo ring (132 cells), level-2 smem only, clamped ----
    if (tid < 132) {
        int lr, lc;
        if (tid < 34)       { lr = 0;         lc = tid;        }
        else if (tid < 68)  { lr = 33;        lc = tid - 34;   }
        else if (tid < 100) { lr = tid - 67;  lc = 0;          }
        else                { lr = tid - 99;  lc = 33;         }
        const int r = min(max(r0g - 1 + lr, 0), 255);
        const int c = min(max(c0g - 1 + lc, 0), 255);

        float l2h, l2v, l2d;
        float2 t0, t1, t2, t3, t4, t5;
        cell_compute(inb, r, c, l2h, l2v, l2d, t0, t1, t2, t3, t4, t5);
        sH[lr * H2_S + lc] = l2h;
        sV[lr * H2_S + lc] = l2v;
        sD[lr * H2_S + lc] = l2d;
    }

    __syncthreads();

    // ---- Part 3: bilinear 2x upsample, 8 horizontal outputs/thread ----
    // out[2k] = 0.25*v[k-1]+0.75*v[k],  out[2k+1] = 0.75*v[k]+0.25*v[k+1]
    #pragma unroll 1
    for (int i = tid; i < 512; i += 256) {
        const int y  = i >> 3;         // 0..63
        const int xo = i & 7;          // col group: x = 8*xo .. 8*xo+7
        const int ky = (y >> 1) + 1;
        const int ry0 = (y & 1) ? ky     : ky - 1;
        const int ry1 = (y & 1) ? ky + 1 : ky;
        const float wy0 = (y & 1) ? 0.75f : 0.25f;
        const float wy1 = 1.0f - wy0;

        const int cb = 4 * xo;               // local level-2 cols cb..cb+5
        const int A0 = ry0 * H2_S + cb;      // 16B-aligned
        const int A1 = ry1 * H2_S + cb;

        const size_t o4 = ((size_t)(oy0 + y) * 512 + ox0 + 8 * xo) >> 2;
        float4* op = (float4*)outb;

        #pragma unroll
        for (int ch = 0; ch < 3; ch++) {
            const float* s = (ch == 0) ? sH : (ch == 1) ? sV : sD;
            const float4 a4 = *(const float4*)(s + A0);
            const float2 a2 = *(const float2*)(s + A0 + 4);
            const float4 b4 = *(const float4*)(s + A1);
            const float2 b2 = *(const float2*)(s + A1 + 4);
            const float m0 = wy0 * a4.x + wy1 * b4.x;
            const float m1 = wy0 * a4.y + wy1 * b4.y;
            const float m2 = wy0 * a4.z + wy1 * b4.z;
            const float m3 = wy0 * a4.w + wy1 * b4.w;
            const float m4 = wy0 * a2.x + wy1 * b2.x;
            const float m5 = wy0 * a2.y + wy1 * b2.y;

            const float4 r0 = make_float4(0.25f * m0 + 0.75f * m1,
                                          0.75f * m1 + 0.25f * m2,
                                          0.25f * m1 + 0.75f * m2,
                                          0.75f * m2 + 0.25f * m3);
            const float4 r1 = make_float4(0.25f * m2 + 0.75f * m3,
                                          0.75f * m3 + 0.25f * m4,
                                          0.25f * m3 + 0.75f * m4,
                                          0.75f * m4 + 0.25f * m5);
            __stcs(op + (size_t)(3 + ch) * 65536 + o4,     r0);
            __stcs(op + (size_t)(3 + ch) * 65536 + o4 + 1, r1);
        }
    }
}

extern "C" void kernel_launch(void* const* d_in, const int* in_sizes, int n_in,
                              void* d_out, int out_size)
{
    const float* x = (const float*)d_in[0];
    float* out = (float*)d_out;
    dim3 grid(512 / TS, 512 / TS, 32);   // (8, 8, 32) = 2048 blocks
    dwt_fused_kernel<<<grid, 256>>>(x, out);
}

// round 8
// speedup vs baseline: 1.2563x; 1.0875x over previous
#include <cuda_runtime.h>

// DWTExtractor: 2-level Haar DWT + bilinear 2x upsample of level-2 details.
// Input:  (32, 1, 1024, 1024) fp32 -> Output: (32, 6, 512, 512) fp32
//          [cH1, cV1, cD1, up(cH2), up(cV2), up(cD2)]
//
// Block = one 64x64 output tile, all 6 channels, one batch image.
// launch_bounds(256,6): ptxas gets ~36-40 regs so the 4 LDG.128 of each input
// patch stay front-batched (per-thread MLP=4). (256,7) forces 32 regs and
// serializes the loads -- measured regression in R5.
//  Part 0: 132-cell halo ring FIRST (clamped == jax resize renorm), level-2
//          smem only; issuing these loads early overlaps them with Part 1.
//  Part 1: central 32x32 level-2 cells, 1 cell/thread, 4 iterations.
//          Lanes map to consecutive float4 columns (fully coalesced LDG.128).
//          Each cell: 4x4 patch -> level-2 coeffs to smem + 2x2 level-1
//          detail block to gmem (float2 streaming stores, coalesced).
//  Part 3: separable half-pixel bilinear (0.75/0.25), 8 outputs/thread,
//          vector LDS (rows 16B-aligned, stride 36), float4 streaming stores.

#define TS    64
#define H2_T  34
#define H2_S  36   // smem row stride (floats): 144B -> 16B-aligned rows

__device__ __forceinline__ void cell_compute(
    const float* __restrict__ inb, int r, int c,
    float& l2h, float& l2v, float& l2d,
    float2& hT, float2& vT, float2& dT,
    float2& hB, float2& vB, float2& dB)
{
    const float4 v0 = *((const float4*)(inb + (size_t)(4 * r    ) * 1024) + c);
    const float4 v1 = *((const float4*)(inb + (size_t)(4 * r + 1) * 1024) + c);
    const float4 v2 = *((const float4*)(inb + (size_t)(4 * r + 2) * 1024) + c);
    const float4 v3 = *((const float4*)(inb + (size_t)(4 * r + 3) * 1024) + c);

    const float s0l = v0.x + v0.y, d0l = v0.x - v0.y;
    const float s0r = v0.z + v0.w, d0r = v0.z - v0.w;
    const float s1l = v1.x + v1.y, d1l = v1.x - v1.y;
    const float s1r = v1.z + v1.w, d1r = v1.z - v1.w;
    const float s2l = v2.x + v2.y, d2l = v2.x - v2.y;
    const float s2r = v2.z + v2.w, d2r = v2.z - v2.w;
    const float s3l = v3.x + v3.y, d3l = v3.x - v3.y;
    const float s3r = v3.z + v3.w, d3r = v3.z - v3.w;

    const float a00 = s0l + s1l, a01 = s0r + s1r;
    const float a10 = s2l + s3l, a11 = s2r + s3r;
    l2h = (a00 - a01 + a10 - a11) * 0.25f;   // 0.5 haar * 0.5 folded cA1
    l2v = (a00 + a01 - a10 - a11) * 0.25f;
    l2d = (a00 - a01 - a10 + a11) * 0.25f;

    hT = make_float2((d0l + d1l) * 0.5f, (d0r + d1r) * 0.5f);
    vT = make_float2((s0l - s1l) * 0.5f, (s0r - s1r) * 0.5f);
    dT = make_float2((d0l - d1l) * 0.5f, (d0r - d1r) * 0.5f);
    hB = make_float2((d2l + d3l) * 0.5f, (d2r + d3r) * 0.5f);
    vB = make_float2((s2l - s3l) * 0.5f, (s2r - s3r) * 0.5f);
    dB = make_float2((d2l - d3l) * 0.5f, (d2r - d3r) * 0.5f);
}

__global__ __launch_bounds__(256, 6)
void dwt_fused_kernel(const float* __restrict__ in, float* __restrict__ out)
{
    __shared__ __align__(16) float sH[H2_T * H2_S];
    __shared__ __align__(16) float sV[H2_T * H2_S];
    __shared__ __align__(16) float sD[H2_T * H2_S];

    const int b   = blockIdx.z;
    const int oy0 = blockIdx.y * TS;
    const int ox0 = blockIdx.x * TS;
    const int tid = threadIdx.x;

    const float* __restrict__ inb  = in  + (size_t)b * 1024 * 1024;
    float* __restrict__       outb = out + (size_t)b * 6 * 512 * 512;

    const int r0g = oy0 >> 1;   // level-2 tile origin on the 256-grid
    const int c0g = ox0 >> 1;

    // ---- Part 0: halo ring (132 cells), level-2 smem only, clamped ----
    if (tid < 132) {
        int lr, lc;
        if (tid < 34)       { lr = 0;         lc = tid;        }
        else if (tid < 68)  { lr = 33;        lc = tid - 34;   }
        else if (tid < 100) { lr = tid - 67;  lc = 0;          }
        else                { lr = tid - 99;  lc = 33;         }
        const int r = min(max(r0g - 1 + lr, 0), 255);
        const int c = min(max(c0g - 1 + lc, 0), 255);

        float l2h, l2v, l2d;
        float2 t0, t1, t2, t3, t4, t5;
        cell_compute(inb, r, c, l2h, l2v, l2d, t0, t1, t2, t3, t4, t5);
        sH[lr * H2_S + lc] = l2h;
        sV[lr * H2_S + lc] = l2v;
        sD[lr * H2_S + lc] = l2d;
    }

    // ---- Part 1: central 32x32 level-2 cells (no clamps, shift indexing) ----
    #pragma unroll 1
    for (int it = 0; it < 4; it++) {
        const int idx = it * 256 + tid;
        const int col = idx & 31;          // lane -> column: coalesced loads
        const int row = idx >> 5;          // 0..31
        const int rr = r0g + row;
        const int cc = c0g + col;

        float l2h, l2v, l2d;
        float2 hT, vT, dT, hB, vB, dB;
        cell_compute(inb, rr, cc, l2h, l2v, l2d, hT, vT, dT, hB, vB, dB);

        sH[(row + 1) * H2_S + col + 1] = l2h;
        sV[(row + 1) * H2_S + col + 1] = l2v;
        sD[(row + 1) * H2_S + col + 1] = l2d;

        // level-1 2x2 block: rows 2rr,2rr+1; cols 2cc,2cc+1 (float2 stores)
        const size_t oT = ((size_t)(2 * rr) * 512 + 2 * cc) >> 1;  // float2 idx
        const size_t oB = oT + 256;
        float2* o2 = (float2*)outb;
        __stcs(o2 + 0 * 131072 + oT, hT);
        __stcs(o2 + 0 * 131072 + oB, hB);
        __stcs(o2 + 1 * 131072 + oT, vT);
        __stcs(o2 + 1 * 131072 + oB, vB);
        __stcs(o2 + 2 * 131072 + oT, dT);
        __stcs(o2 + 2 * 131072 + oB, dB);
    }

    __syncthreads();

    // ---- Part 3: bilinear 2x upsample, 8 horizontal outputs/thread ----
    // out[2k] = 0.25*v[k-1]+0.75*v[k],  out[2k+1] = 0.75*v[k]+0.25*v[k+1]
    #pragma unroll 1
    for (int i = tid; i < 512; i += 256) {
        const int y  = i >> 3;         // 0..63
        const int xo = i & 7;          // col group: x = 8*xo .. 8*xo+7
        const int ky = (y >> 1) + 1;
        const int ry0 = (y & 1) ? ky     : ky - 1;
        const int ry1 = (y & 1) ? ky + 1 : ky;
        const float wy0 = (y & 1) ? 0.75f : 0.25f;
        const float wy1 = 1.0f - wy0;

        const int cb = 4 * xo;               // local level-2 cols cb..cb+5
        const int A0 = ry0 * H2_S + cb;      // 16B-aligned
        const int A1 = ry1 * H2_S + cb;

        const size_t o4 = ((size_t)(oy0 + y) * 512 + ox0 + 8 * xo) >> 2;
        float4* op = (float4*)outb;

        #pragma unroll
        for (int ch = 0; ch < 3; ch++) {
            const float* s = (ch == 0) ? sH : (ch == 1) ? sV : sD;
            const float4 a4 = *(const float4*)(s + A0);
            const float2 a2 = *(const float2*)(s + A0 + 4);
            const float4 b4 = *(const float4*)(s + A1);
            const float2 b2 = *(const float2*)(s + A1 + 4);
            const float m0 = wy0 * a4.x + wy1 * b4.x;
            const float m1 = wy0 * a4.y + wy1 * b4.y;
            const float m2 = wy0 * a4.z + wy1 * b4.z;
            const float m3 = wy0 * a4.w + wy1 * b4.w;
            const float m4 = wy0 * a2.x + wy1 * b2.x;
            const float m5 = wy0 * a2.y + wy1 * b2.y;

            const float4 r0 = make_float4(0.25f * m0 + 0.75f * m1,
                                          0.75f * m1 + 0.25f * m2,
                                          0.25f * m1 + 0.75f * m2,
                                          0.75f * m2 + 0.25f * m3);
            const float4 r1 = make_float4(0.25f * m2 + 0.75f * m3,
                                          0.75f * m3 + 0.25f * m4,
                                          0.25f * m3 + 0.75f * m4,
                                          0.75f * m4 + 0.25f * m5);
            __stcs(op + (size_t)(3 + ch) * 65536 + o4,     r0);
            __stcs(op + (size_t)(3 + ch) * 65536 + o4 + 1, r1);
        }
    }
}

extern "C" void kernel_launch(void* const* d_in, const int* in_sizes, int n_in,
                              void* d_out, int out_size)
{
    const float* x = (const float*)d_in[0];
    float* out = (float*)d_out;
    dim3 grid(512 / TS, 512 / TS, 32);   // (8, 8, 32) = 2048 blocks
    dwt_fused_kernel<<<grid, 256>>>(x, out);
}

// round 9
// speedup vs baseline: 1.3106x; 1.0432x over previous
#include <cuda_runtime.h>

// DWTExtractor: 2-level Haar DWT + bilinear 2x upsample of level-2 details.
// Input:  (32, 1, 1024, 1024) fp32 -> Output: (32, 6, 512, 512) fp32
//          [cH1, cV1, cD1, up(cH2), up(cV2), up(cD2)]
//
// Latency-bound kernel (no pipe saturated) -> raise per-thread MLP.
// Block = one 64x64 output tile. Each thread in the central pass handles TWO
// vertically-stacked level-2 cells: 8 front-batched LDG.128 (all warp-
// contiguous 512B; NEVER pair horizontally - lane->column stays dense).
// launch_bounds(256,4) so ptxas is free up to 64 regs (no forced load
// serialization).
//  Part 0: 132-cell halo ring (clamped == jax resize weight renorm),
//          level-2 smem only, issued first to overlap with Part 1.
//  Part 1: central 32x32 level-2 cells, 2 cells/thread, 2 iterations.
//          Each cell: 4x4 patch -> level-2 coeffs to smem + 2x2 level-1
//          block to gmem (float2 streaming stores, coalesced).
//  Part 3: separable half-pixel bilinear (0.75/0.25), 8 outputs/thread,
//          vector LDS (rows 16B-aligned, stride 36), float4 streaming stores.

#define TS    64
#define H2_T  34
#define H2_S  36   // smem row stride (floats): 144B -> 16B-aligned rows

// Compute level-2 + level-1 coefficients from a loaded 4x4 patch.
__device__ __forceinline__ void patch_compute(
    const float4 v0, const float4 v1, const float4 v2, const float4 v3,
    float& l2h, float& l2v, float& l2d,
    float2& hT, float2& vT, float2& dT,
    float2& hB, float2& vB, float2& dB)
{
    const float s0l = v0.x + v0.y, d0l = v0.x - v0.y;
    const float s0r = v0.z + v0.w, d0r = v0.z - v0.w;
    const float s1l = v1.x + v1.y, d1l = v1.x - v1.y;
    const float s1r = v1.z + v1.w, d1r = v1.z - v1.w;
    const float s2l = v2.x + v2.y, d2l = v2.x - v2.y;
    const float s2r = v2.z + v2.w, d2r = v2.z - v2.w;
    const float s3l = v3.x + v3.y, d3l = v3.x - v3.y;
    const float s3r = v3.z + v3.w, d3r = v3.z - v3.w;

    const float a00 = s0l + s1l, a01 = s0r + s1r;
    const float a10 = s2l + s3l, a11 = s2r + s3r;
    l2h = (a00 - a01 + a10 - a11) * 0.25f;   // 0.5 haar * 0.5 folded cA1
    l2v = (a00 + a01 - a10 - a11) * 0.25f;
    l2d = (a00 - a01 - a10 + a11) * 0.25f;

    hT = make_float2((d0l + d1l) * 0.5f, (d0r + d1r) * 0.5f);
    vT = make_float2((s0l - s1l) * 0.5f, (s0r - s1r) * 0.5f);
    dT = make_float2((d0l - d1l) * 0.5f, (d0r - d1r) * 0.5f);
    hB = make_float2((d2l + d3l) * 0.5f, (d2r + d3r) * 0.5f);
    vB = make_float2((s2l - s3l) * 0.5f, (s2r - s3r) * 0.5f);
    dB = make_float2((d2l - d3l) * 0.5f, (d2r - d3r) * 0.5f);
}

__global__ __launch_bounds__(256, 4)
void dwt_fused_kernel(const float* __restrict__ in, float* __restrict__ out)
{
    __shared__ __align__(16) float sH[H2_T * H2_S];
    __shared__ __align__(16) float sV[H2_T * H2_S];
    __shared__ __align__(16) float sD[H2_T * H2_S];

    const int b   = blockIdx.z;
    const int oy0 = blockIdx.y * TS;
    const int ox0 = blockIdx.x * TS;
    const int tid = threadIdx.x;

    const float* __restrict__ inb  = in  + (size_t)b * 1024 * 1024;
    float* __restrict__       outb = out + (size_t)b * 6 * 512 * 512;

    const int r0g = oy0 >> 1;   // level-2 tile origin on the 256-grid
    const int c0g = ox0 >> 1;

    // ---- Part 0: halo ring (132 cells), level-2 smem only, clamped ----
    if (tid < 132) {
        int lr, lc;
        if (tid < 34)       { lr = 0;         lc = tid;        }
        else if (tid < 68)  { lr = 33;        lc = tid - 34;   }
        else if (tid < 100) { lr = tid - 67;  lc = 0;          }
        else                { lr = tid - 99;  lc = 33;         }
        const int r = min(max(r0g - 1 + lr, 0), 255);
        const int c = min(max(c0g - 1 + lc, 0), 255);

        const float4* p = (const float4*)(inb + (size_t)(4 * r) * 1024) + c;
        const float4 v0 = p[0], v1 = p[256], v2 = p[512], v3 = p[768];
        float l2h, l2v, l2d;
        float2 t0, t1, t2, t3, t4, t5;
        patch_compute(v0, v1, v2, v3, l2h, l2v, l2d, t0, t1, t2, t3, t4, t5);
        sH[lr * H2_S + lc] = l2h;
        sV[lr * H2_S + lc] = l2v;
        sD[lr * H2_S + lc] = l2d;
    }

    // ---- Part 1: central 32x32 cells, 2 vertical cells/thread ----
    float2* const o2 = (float2*)outb;
    #pragma unroll 1
    for (int it = 0; it < 2; it++) {
        const int col  = tid & 31;               // lane -> column (coalesced)
        const int rowA = (tid >> 5) + it * 8;    // 0..15
        const int rowB = rowA + 16;              // 16..31
        const int rrA = r0g + rowA;
        const int rrB = r0g + rowB;
        const int cc  = c0g + col;

        // 8 front-batched LDG.128 (independent -> MLP 8)
        const float4* pA = (const float4*)(inb + (size_t)(4 * rrA) * 1024) + cc;
        const float4* pB = (const float4*)(inb + (size_t)(4 * rrB) * 1024) + cc;
        const float4 a0 = pA[0], a1 = pA[256], a2 = pA[512], a3 = pA[768];
        const float4 b0 = pB[0], b1 = pB[256], b2 = pB[512], b3 = pB[768];

        float l2h, l2v, l2d;
        float2 hT, vT, dT, hB, vB, dB;

        // cell A
        patch_compute(a0, a1, a2, a3, l2h, l2v, l2d, hT, vT, dT, hB, vB, dB);
        sH[(rowA + 1) * H2_S + col + 1] = l2h;
        sV[(rowA + 1) * H2_S + col + 1] = l2v;
        sD[(rowA + 1) * H2_S + col + 1] = l2d;
        {
            const size_t oT = ((size_t)(2 * rrA) * 512 + 2 * cc) >> 1;
            const size_t oB = oT + 256;
            __stcs(o2 + 0 * 131072 + oT, hT);
            __stcs(o2 + 0 * 131072 + oB, hB);
            __stcs(o2 + 1 * 131072 + oT, vT);
            __stcs(o2 + 1 * 131072 + oB, vB);
            __stcs(o2 + 2 * 131072 + oT, dT);
            __stcs(o2 + 2 * 131072 + oB, dB);
        }

        // cell B
        patch_compute(b0, b1, b2, b3, l2h, l2v, l2d, hT, vT, dT, hB, vB, dB);
        sH[(rowB + 1) * H2_S + col + 1] = l2h;
        sV[(rowB + 1) * H2_S + col + 1] = l2v;
        sD[(rowB + 1) * H2_S + col + 1] = l2d;
        {
            const size_t oT = ((size_t)(2 * rrB) * 512 + 2 * cc) >> 1;
            const size_t oB = oT + 256;
            __stcs(o2 + 0 * 131072 + oT, hT);
            __stcs(o2 + 0 * 131072 + oB, hB);
            __stcs(o2 + 1 * 131072 + oT, vT);
            __stcs(o2 + 1 * 131072 + oB, vB);
            __stcs(o2 + 2 * 131072 + oT, dT);
            __stcs(o2 + 2 * 131072 + oB, dB);
        }
    }

    __syncthreads();

    // ---- Part 3: bilinear 2x upsample, 8 horizontal outputs/thread ----
    // out[2k] = 0.25*v[k-1]+0.75*v[k],  out[2k+1] = 0.75*v[k]+0.25*v[k+1]
    #pragma unroll 1
    for (int i = tid; i < 512; i += 256) {
        const int y  = i >> 3;         // 0..63
        const int xo = i & 7;          // col group: x = 8*xo .. 8*xo+7
        const int ky = (y >> 1) + 1;
        const int ry0 = (y & 1) ? ky     : ky - 1;
        const int ry1 = (y & 1) ? ky + 1 : ky;
        const float wy0 = (y & 1) ? 0.75f : 0.25f;
        const float wy1 = 1.0f - wy0;

        const int cb = 4 * xo;               // local level-2 cols cb..cb+5
        const int A0 = ry0 * H2_S + cb;      // 16B-aligned
        const int A1 = ry1 * H2_S + cb;

        const size_t o4 = ((size_t)(oy0 + y) * 512 + ox0 + 8 * xo) >> 2;
        float4* op = (float4*)outb;

        #pragma unroll
        for (int ch = 0; ch < 3; ch++) {
            const float* s = (ch == 0) ? sH : (ch == 1) ? sV : sD;
            const float4 a4 = *(const float4*)(s + A0);
            const float2 a2 = *(const float2*)(s + A0 + 4);
            const float4 b4 = *(const float4*)(s + A1);
            const float2 b2 = *(const float2*)(s + A1 + 4);
            const float m0 = wy0 * a4.x + wy1 * b4.x;
            const float m1 = wy0 * a4.y + wy1 * b4.y;
            const float m2 = wy0 * a4.z + wy1 * b4.z;
            const float m3 = wy0 * a4.w + wy1 * b4.w;
            const float m4 = wy0 * a2.x + wy1 * b2.x;
            const float m5 = wy0 * a2.y + wy1 * b2.y;

            const float4 r0 = make_float4(0.25f * m0 + 0.75f * m1,
                                          0.75f * m1 + 0.25f * m2,
                                          0.25f * m1 + 0.75f * m2,
                                          0.75f * m2 + 0.25f * m3);
            const float4 r1 = make_float4(0.25f * m2 + 0.75f * m3,
                                          0.75f * m3 + 0.25f * m4,
                                          0.25f * m3 + 0.75f * m4,
                                          0.75f * m4 + 0.25f * m5);
            __stcs(op + (size_t)(3 + ch) * 65536 + o4,     r0);
            __stcs(op + (size_t)(3 + ch) * 65536 + o4 + 1, r1);
        }
    }
}

extern "C" void kernel_launch(void* const* d_in, const int* in_sizes, int n_in,
                              void* d_out, int out_size)
{
    const float* x = (const float*)d_in[0];
    float* out = (float*)d_out;
    dim3 grid(512 / TS, 512 / TS, 32);   // (8, 8, 32) = 2048 blocks
    dwt_fused_kernel<<<grid, 256>>>(x, out);
}